// round 10
// baseline (speedup 1.0000x reference)
#include <cuda_runtime.h>
#include <cstdint>

#define N_NODES 50000
#define N_EDGES 800000

// ---- fused-weight / node-projection scratch (__device__ globals; no alloc) ----
__device__ float g_Wc[96 * 64];        // [k][n]: rows 0..63 = W1[64:128]@W2a, rows 64..95 = W2[64:96]
__device__ float g_AD[64 * 128];       // cols 0..63: A, cols 64..127: D
__device__ float g_bias[64];           // b1@W2a + b2
__device__ float g_PQ[(size_t)N_NODES * 128];  // per-node: P (0..63), Q (64..127)

__device__ __forceinline__ uint32_t f2tf32(float x) {
    uint32_t r;
    asm("cvt.rna.tf32.f32 %0, %1;" : "=r"(r) : "f"(x));
    return r;
}
// streaming store (evict-first)
__device__ __forceinline__ void stg_cs(float* p, float2 v) {
    asm volatile("st.global.cs.v2.f32 [%0], {%1,%2};" :: "l"(p), "f"(v.x), "f"(v.y));
}
__device__ __forceinline__ void mma_tf32(float c[4], const uint32_t a[4], const uint32_t b[2]) {
    asm volatile(
        "mma.sync.aligned.m16n8k8.row.col.f32.tf32.tf32.f32 "
        "{%0,%1,%2,%3}, {%4,%5,%6,%7}, {%8,%9}, {%0,%1,%2,%3};"
        : "+f"(c[0]), "+f"(c[1]), "+f"(c[2]), "+f"(c[3])
        : "r"(a[0]), "r"(a[1]), "r"(a[2]), "r"(a[3]), "r"(b[0]), "r"(b[1]));
}

// ---------------------------------------------------------------------------
// Kernel 1: fuse weights. 48 blocks x 256 thr, one output per thread.
// ---------------------------------------------------------------------------
__global__ void __launch_bounds__(256) prep_kernel(
    const float* __restrict__ W1, const float* __restrict__ b1,
    const float* __restrict__ W2, const float* __restrict__ b2) {
    __shared__ float W2s[64 * 64];
    int t = threadIdx.x;
    for (int i = t; i < 64 * 64; i += 256) W2s[i] = W2[i];
    __syncthreads();

    int o = blockIdx.x * 256 + t;   // 12288 = 192*64 exactly
    {
        int i = o >> 6;
        int j = o & 63;
        float s0 = 0.f, s1 = 0.f, s2 = 0.f, s3 = 0.f;
#pragma unroll
        for (int k = 0; k < 64; k += 4) {
            float4 w = *(const float4*)(W1 + i * 64 + k);
            s0 = fmaf(w.x, W2s[(k + 0) * 64 + j], s0);
            s1 = fmaf(w.y, W2s[(k + 1) * 64 + j], s1);
            s2 = fmaf(w.z, W2s[(k + 2) * 64 + j], s2);
            s3 = fmaf(w.w, W2s[(k + 3) * 64 + j], s3);
        }
        float s = (s0 + s1) + (s2 + s3);
        if (i < 64)       g_AD[i * 128 + j] = s;                 // A
        else if (i < 128) g_Wc[(i - 64) * 64 + j] = s;           // B (e_h block)
        else              g_AD[(i - 128) * 128 + 64 + j] = s;    // D
    }
    if (blockIdx.x == 0) {
        for (int i = t; i < 32 * 64; i += 256) g_Wc[64 * 64 + i] = W2[64 * 64 + i];
        if (t < 64) {
            float s0 = 0.f, s1 = 0.f;
#pragma unroll
            for (int k = 0; k < 64; k += 2) {
                s0 = fmaf(b1[k], W2s[k * 64 + t], s0);
                s1 = fmaf(b1[k + 1], W2s[(k + 1) * 64 + t], s1);
            }
            g_bias[t] = s0 + s1 + b2[t];
        }
    }
}

// ---------------------------------------------------------------------------
// Kernel 2: node projections PQ = h @ [A|D] via tf32 mma.
// Tile: 64 nodes x 128 cols, K=64 (8 K-steps). 8 warps = 2 M-groups x 4 N-groups.
// ---------------------------------------------------------------------------
#define NA_STRIDE 68                    // 68 % 32 == 4 -> A frag bank = 4*lq+lr, conflict-free
#define NB_STRIDE 136                   // 136 % 32 == 8 -> B frag bank = 8*lr+lq, conflict-free
#define NSM_A_OFF 0
#define NSM_B_OFF (64 * NA_STRIDE)      // 4352 words
#define NSM_WORDS (NSM_B_OFF + 64 * NB_STRIDE)   // 13056 words = 52224 B

__global__ void __launch_bounds__(256) node_kernel(const float* __restrict__ h) {
    extern __shared__ uint32_t nsm[];
    uint32_t* As = nsm + NSM_A_OFF;
    uint32_t* Bs = nsm + NSM_B_OFF;

    int t = threadIdx.x;
    int wid = t >> 5;
    int lane = t & 31;
    int mw = wid >> 2;        // 0..1 -> rows [mw*32, +32)
    int nw = wid & 3;         // 0..3 -> cols [nw*32, +32)
    int lq = lane >> 2;
    int lr = lane & 3;

    int n0 = blockIdx.x * 64;

    // stage B = g_AD [64 K][128 cols] -> tf32, stride 136
#pragma unroll
    for (int j = 0; j < 8; j++) {
        int i = t + j * 256;            // 0..2047, each covers 4 words
        int k = i >> 5;
        int c4 = (i & 31) << 2;
        float4 v = *(const float4*)(g_AD + k * 128 + c4);
        uint4 w = make_uint4(f2tf32(v.x), f2tf32(v.y), f2tf32(v.z), f2tf32(v.w));
        *(uint4*)(Bs + k * NB_STRIDE + c4) = w;
    }
    // stage A = h tile [64 rows][64 K] -> tf32, stride 68 (clamp tail rows)
#pragma unroll
    for (int j = 0; j < 4; j++) {
        int i = t + j * 256;            // 0..1023
        int m = i >> 4;
        int c4 = (i & 15) << 2;
        int n = n0 + m;
        if (n >= N_NODES) n = N_NODES - 1;
        float4 v = *(const float4*)(h + (size_t)n * 64 + c4);
        uint4 w = make_uint4(f2tf32(v.x), f2tf32(v.y), f2tf32(v.z), f2tf32(v.w));
        *(uint4*)(As + m * NA_STRIDE + c4) = w;
    }
    __syncthreads();

    float c[2][4][4];
#pragma unroll
    for (int mf = 0; mf < 2; mf++)
#pragma unroll
        for (int nf = 0; nf < 4; nf++)
#pragma unroll
            for (int i = 0; i < 4; i++) c[mf][nf][i] = 0.f;

#pragma unroll
    for (int ks = 0; ks < 8; ks++) {
        int kb = ks * 8;
        uint32_t a[2][4];
#pragma unroll
        for (int mf = 0; mf < 2; mf++) {
            const uint32_t* ap = As + (mw * 32 + mf * 16 + lq) * NA_STRIDE + kb + lr;
            a[mf][0] = ap[0];
            a[mf][1] = ap[8 * NA_STRIDE];
            a[mf][2] = ap[4];
            a[mf][3] = ap[8 * NA_STRIDE + 4];
        }
        uint32_t b[4][2];
#pragma unroll
        for (int nf = 0; nf < 4; nf++) {
            const uint32_t* bp = Bs + (kb + lr) * NB_STRIDE + nw * 32 + nf * 8 + lq;
            b[nf][0] = bp[0];
            b[nf][1] = bp[4 * NB_STRIDE];
        }
#pragma unroll
        for (int mf = 0; mf < 2; mf++)
#pragma unroll
            for (int nf = 0; nf < 4; nf++)
                mma_tf32(c[mf][nf], a[mf], b[nf]);
    }

    // store to g_PQ (predicated on node bound)
#pragma unroll
    for (int mf = 0; mf < 2; mf++)
#pragma unroll
        for (int half = 0; half < 2; half++) {
            int r = mw * 32 + mf * 16 + half * 8 + lq;
            int n = n0 + r;
            if (n < N_NODES) {
#pragma unroll
                for (int nf = 0; nf < 4; nf++) {
                    int col = nw * 32 + nf * 8 + 2 * lr;
                    float2 v = make_float2(c[mf][nf][half * 2 + 0], c[mf][nf][half * 2 + 1]);
                    *(float2*)(g_PQ + (size_t)n * 128 + col) = v;
                }
            }
        }
}

// ---------------------------------------------------------------------------
// Kernel 3: tf32 mma.sync edge GEMM. TILE_M=64 -> 53.5KB SMEM -> 4 CTAs/SM.
// Streams evict-first, PQ gathers default, indices prefetched pre-mainloop.
// 8 warps = 4 M-groups (16 rows) x 2 N-groups (32 cols).
// ---------------------------------------------------------------------------
#define TILE_M 64
#define NTILES (N_EDGES / TILE_M)       // 12500
#define EDGE_GRID 592                   // 148 SMs x 4 CTAs

#define A_STRIDE 100
#define B_STRIDE 72
#define SMEM_A_OFF 0
#define SMEM_B_OFF (TILE_M * A_STRIDE)             // 6400 words
#define SMEM_BIAS_OFF (SMEM_B_OFF + 96 * B_STRIDE) // 13312 words
#define SMEM_WORDS (SMEM_BIAS_OFF + 64)            // 13376 words = 53504 B

__global__ void __launch_bounds__(256, 4) edge_kernel(
    const float* __restrict__ e_h, const float* __restrict__ ext,
    const int* __restrict__ src, const int* __restrict__ dst,
    float* __restrict__ out)
{
    extern __shared__ uint32_t smw[];
    uint32_t* As = smw + SMEM_A_OFF;
    uint32_t* Bs = smw + SMEM_B_OFF;
    float*  bias = (float*)(smw + SMEM_BIAS_OFF);

    int t = threadIdx.x;
    int wid = t >> 5;
    int lane = t & 31;
    int mw = wid & 3;         // 0..3 -> rows [mw*16, +16)
    int nw = wid >> 2;        // 0..1 -> cols [nw*32, +32)
    int lq = lane >> 2;
    int lr = lane & 3;

    // stage B (weights, tf32, [k][n] stride 72) + bias — once per CTA
    for (int i = t; i < 96 * 64; i += 256) {
        int k = i >> 6;
        int n = i & 63;
        Bs[k * B_STRIDE + n] = f2tf32(g_Wc[i]);
    }
    if (t < 64) bias[t] = g_bias[t];

    // bias regs (4 x float2 per thread, this thread's columns)
    __syncthreads();
    float2 bv[4];
#pragma unroll
    for (int nf = 0; nf < 4; nf++)
        bv[nf] = *(const float2*)(bias + nw * 32 + nf * 8 + 2 * lr);

    for (int tile = blockIdx.x; tile < NTILES; tile += EDGE_GRID) {
        int e0 = tile * TILE_M;
        __syncthreads();   // prev-iter LDS of As done

        // ---- stage A: e_h -> cols 0..63 (streaming, cvt tf32): 4 x float4/thread
#pragma unroll
        for (int j = 0; j < 4; j++) {
            int i = t + j * 256;
            int m = i >> 4;
            int c4 = (i & 15) << 2;
            float4 v = __ldcs((const float4*)(e_h + (size_t)(e0 + m) * 64 + c4));
            uint4 w = make_uint4(f2tf32(v.x), f2tf32(v.y), f2tf32(v.z), f2tf32(v.w));
            *(uint4*)(As + m * A_STRIDE + c4) = w;
        }
        // ---- stage A: ext -> cols 64..95: 2 x float4/thread
#pragma unroll
        for (int j = 0; j < 2; j++) {
            int i = t + j * 256;
            int m = i >> 3;
            int c4 = (i & 7) << 2;
            float4 v = __ldcs((const float4*)(ext + (size_t)(e0 + m) * 32 + c4));
            uint4 w = make_uint4(f2tf32(v.x), f2tf32(v.y), f2tf32(v.z), f2tf32(v.w));
            *(uint4*)(As + m * A_STRIDE + 64 + c4) = w;
        }

        // ---- prefetch gather indices (2 edge rows/thread) ----
        int er0 = e0 + mw * 16 + lq;
        int er1 = er0 + 8;
        int s0 = src[er0], d0 = dst[er0];
        int s1 = src[er1], d1 = dst[er1];
        __syncthreads();

        // ---- mma mainloop: 12 K-steps of 8 ----
        float c[4][4];
#pragma unroll
        for (int nf = 0; nf < 4; nf++)
#pragma unroll
            for (int i = 0; i < 4; i++) c[nf][i] = 0.f;

#pragma unroll
        for (int ks = 0; ks < 12; ks++) {
            int kb = ks * 8;
            uint32_t a[4];
            {
                const uint32_t* ap = As + (mw * 16 + lq) * A_STRIDE + kb + lr;
                a[0] = ap[0];
                a[1] = ap[8 * A_STRIDE];
                a[2] = ap[4];
                a[3] = ap[8 * A_STRIDE + 4];
            }
            uint32_t b[4][2];
#pragma unroll
            for (int nf = 0; nf < 4; nf++) {
                const uint32_t* bp = Bs + (kb + lr) * B_STRIDE + nw * 32 + nf * 8 + lq;
                b[nf][0] = bp[0];
                b[nf][1] = bp[4 * B_STRIDE];
            }
#pragma unroll
            for (int nf = 0; nf < 4; nf++)
                mma_tf32(c[nf], a, b[nf]);
        }

        // ---- epilogue: +P[src] +Q[dst] +bias, ReLU, streaming store ----
#pragma unroll
        for (int half = 0; half < 2; half++) {
            int e = half ? er1 : er0;
            int s = half ? s1 : s0;
            int d = half ? d1 : d0;
            const float* P = g_PQ + (size_t)s * 128;
            const float* Q = g_PQ + (size_t)d * 128 + 64;
#pragma unroll
            for (int nf = 0; nf < 4; nf++) {
                int col = nw * 32 + nf * 8 + 2 * lr;
                float2 p = __ldg((const float2*)(P + col));
                float2 q = __ldg((const float2*)(Q + col));
                float cx = c[nf][half * 2 + 0];
                float cy = c[nf][half * 2 + 1];
                float2 rv;
                rv.x = fmaxf(cx + p.x + q.x + bv[nf].x, 0.f);
                rv.y = fmaxf(cy + p.y + q.y + bv[nf].y, 0.f);
                stg_cs(out + (size_t)e * 64 + col, rv);
            }
        }
    }
}

// ---------------------------------------------------------------------------
extern "C" void kernel_launch(void* const* d_in, const int* in_sizes, int n_in,
                              void* d_out, int out_size) {
    const float* h   = (const float*)d_in[0];
    const float* e_h = (const float*)d_in[1];
    const float* ext = (const float*)d_in[2];
    const float* W1  = (const float*)d_in[3];
    const float* b1  = (const float*)d_in[4];
    const float* W2  = (const float*)d_in[5];
    const float* b2  = (const float*)d_in[6];
    const int*   src = (const int*)d_in[7];
    const int*   dst = (const int*)d_in[8];
    float* out = (float*)d_out;

    static bool attr_set = false;
    if (!attr_set) {
        cudaFuncSetAttribute(edge_kernel, cudaFuncAttributeMaxDynamicSharedMemorySize,
                             SMEM_WORDS * 4);
        cudaFuncSetAttribute(node_kernel, cudaFuncAttributeMaxDynamicSharedMemorySize,
                             NSM_WORDS * 4);
        attr_set = true;
    }

    prep_kernel<<<48, 256>>>(W1, b1, W2, b2);
    node_kernel<<<(N_NODES + 63) / 64, 256, NSM_WORDS * 4>>>(h);
    edge_kernel<<<EDGE_GRID, 256, SMEM_WORDS * 4>>>(e_h, ext, src, dst, out);
}

// round 11
// speedup vs baseline: 1.1967x; 1.1967x over previous
#include <cuda_runtime.h>
#include <cstdint>

#define N_NODES 50000
#define N_EDGES 800000

// ---- fused-weight / node-projection scratch (__device__ globals; no alloc) ----
__device__ float g_Wc[96 * 64];        // [k][n]: rows 0..63 = W1[64:128]@W2a, rows 64..95 = W2[64:96]
__device__ float g_AD[64 * 128];       // cols 0..63: A, cols 64..127: D
__device__ float g_bias[64];           // b1@W2a + b2
__device__ float g_PQ[(size_t)N_NODES * 128];  // per-node: P (0..63), Q (64..127)

__device__ __forceinline__ uint32_t f2tf32(float x) {
    uint32_t r;
    asm("cvt.rna.tf32.f32 %0, %1;" : "=r"(r) : "f"(x));
    return r;
}
// streaming store (evict-first)
__device__ __forceinline__ void stg_cs(float* p, float2 v) {
    asm volatile("st.global.cs.v2.f32 [%0], {%1,%2};" :: "l"(p), "f"(v.x), "f"(v.y));
}
__device__ __forceinline__ void mma_tf32(float c[4], const uint32_t a[4], const uint32_t b[2]) {
    asm volatile(
        "mma.sync.aligned.m16n8k8.row.col.f32.tf32.tf32.f32 "
        "{%0,%1,%2,%3}, {%4,%5,%6,%7}, {%8,%9}, {%0,%1,%2,%3};"
        : "+f"(c[0]), "+f"(c[1]), "+f"(c[2]), "+f"(c[3])
        : "r"(a[0]), "r"(a[1]), "r"(a[2]), "r"(a[3]), "r"(b[0]), "r"(b[1]));
}

// ---------------------------------------------------------------------------
// Kernel 1: fuse weights. 48 blocks x 256 thr, one output per thread.
// ---------------------------------------------------------------------------
__global__ void __launch_bounds__(256) prep_kernel(
    const float* __restrict__ W1, const float* __restrict__ b1,
    const float* __restrict__ W2, const float* __restrict__ b2) {
    __shared__ float W2s[64 * 64];
    int t = threadIdx.x;
    for (int i = t; i < 64 * 64; i += 256) W2s[i] = W2[i];
    __syncthreads();

    int o = blockIdx.x * 256 + t;   // 12288 = 192*64 exactly
    {
        int i = o >> 6;
        int j = o & 63;
        float s0 = 0.f, s1 = 0.f, s2 = 0.f, s3 = 0.f;
#pragma unroll
        for (int k = 0; k < 64; k += 4) {
            float4 w = *(const float4*)(W1 + i * 64 + k);
            s0 = fmaf(w.x, W2s[(k + 0) * 64 + j], s0);
            s1 = fmaf(w.y, W2s[(k + 1) * 64 + j], s1);
            s2 = fmaf(w.z, W2s[(k + 2) * 64 + j], s2);
            s3 = fmaf(w.w, W2s[(k + 3) * 64 + j], s3);
        }
        float s = (s0 + s1) + (s2 + s3);
        if (i < 64)       g_AD[i * 128 + j] = s;                 // A
        else if (i < 128) g_Wc[(i - 64) * 64 + j] = s;           // B (e_h block)
        else              g_AD[(i - 128) * 128 + 64 + j] = s;    // D
    }
    if (blockIdx.x == 0) {
        for (int i = t; i < 32 * 64; i += 256) g_Wc[64 * 64 + i] = W2[64 * 64 + i];
        if (t < 64) {
            float s0 = 0.f, s1 = 0.f;
#pragma unroll
            for (int k = 0; k < 64; k += 2) {
                s0 = fmaf(b1[k], W2s[k * 64 + t], s0);
                s1 = fmaf(b1[k + 1], W2s[(k + 1) * 64 + t], s1);
            }
            g_bias[t] = s0 + s1 + b2[t];
        }
    }
}

// ---------------------------------------------------------------------------
// Kernel 2: node projections PQ = h @ [A|D] via tf32 mma (R10 version, ~9us).
// Tile: 64 nodes x 128 cols, K=64 (8 K-steps). 8 warps = 2 M-groups x 4 N-groups.
// ---------------------------------------------------------------------------
#define NA_STRIDE 68                    // 68 % 32 == 4 -> A frag conflict-free
#define NB_STRIDE 136                   // 136 % 32 == 8 -> B frag conflict-free
#define NSM_A_OFF 0
#define NSM_B_OFF (64 * NA_STRIDE)      // 4352 words
#define NSM_WORDS (NSM_B_OFF + 64 * NB_STRIDE)   // 13056 words = 52224 B

__global__ void __launch_bounds__(256) node_kernel(const float* __restrict__ h) {
    extern __shared__ uint32_t nsm[];
    uint32_t* As = nsm + NSM_A_OFF;
    uint32_t* Bs = nsm + NSM_B_OFF;

    int t = threadIdx.x;
    int wid = t >> 5;
    int lane = t & 31;
    int mw = wid >> 2;        // 0..1 -> rows [mw*32, +32)
    int nw = wid & 3;         // 0..3 -> cols [nw*32, +32)
    int lq = lane >> 2;
    int lr = lane & 3;

    int n0 = blockIdx.x * 64;

    // stage B = g_AD [64 K][128 cols] -> tf32, stride 136
#pragma unroll
    for (int j = 0; j < 8; j++) {
        int i = t + j * 256;
        int k = i >> 5;
        int c4 = (i & 31) << 2;
        float4 v = *(const float4*)(g_AD + k * 128 + c4);
        uint4 w = make_uint4(f2tf32(v.x), f2tf32(v.y), f2tf32(v.z), f2tf32(v.w));
        *(uint4*)(Bs + k * NB_STRIDE + c4) = w;
    }
    // stage A = h tile [64 rows][64 K] -> tf32, stride 68 (clamp tail rows)
#pragma unroll
    for (int j = 0; j < 4; j++) {
        int i = t + j * 256;
        int m = i >> 4;
        int c4 = (i & 15) << 2;
        int n = n0 + m;
        if (n >= N_NODES) n = N_NODES - 1;
        float4 v = *(const float4*)(h + (size_t)n * 64 + c4);
        uint4 w = make_uint4(f2tf32(v.x), f2tf32(v.y), f2tf32(v.z), f2tf32(v.w));
        *(uint4*)(As + m * NA_STRIDE + c4) = w;
    }
    __syncthreads();

    float c[2][4][4];
#pragma unroll
    for (int mf = 0; mf < 2; mf++)
#pragma unroll
        for (int nf = 0; nf < 4; nf++)
#pragma unroll
            for (int i = 0; i < 4; i++) c[mf][nf][i] = 0.f;

#pragma unroll
    for (int ks = 0; ks < 8; ks++) {
        int kb = ks * 8;
        uint32_t a[2][4];
#pragma unroll
        for (int mf = 0; mf < 2; mf++) {
            const uint32_t* ap = As + (mw * 32 + mf * 16 + lq) * NA_STRIDE + kb + lr;
            a[mf][0] = ap[0];
            a[mf][1] = ap[8 * NA_STRIDE];
            a[mf][2] = ap[4];
            a[mf][3] = ap[8 * NA_STRIDE + 4];
        }
        uint32_t b[4][2];
#pragma unroll
        for (int nf = 0; nf < 4; nf++) {
            const uint32_t* bp = Bs + (kb + lr) * NB_STRIDE + nw * 32 + nf * 8 + lq;
            b[nf][0] = bp[0];
            b[nf][1] = bp[4 * NB_STRIDE];
        }
#pragma unroll
        for (int mf = 0; mf < 2; mf++)
#pragma unroll
            for (int nf = 0; nf < 4; nf++)
                mma_tf32(c[mf][nf], a[mf], b[nf]);
    }

    // store to g_PQ (predicated on node bound)
#pragma unroll
    for (int mf = 0; mf < 2; mf++)
#pragma unroll
        for (int half = 0; half < 2; half++) {
            int r = mw * 32 + mf * 16 + half * 8 + lq;
            int n = n0 + r;
            if (n < N_NODES) {
#pragma unroll
                for (int nf = 0; nf < 4; nf++) {
                    int col = nw * 32 + nf * 8 + 2 * lr;
                    float2 v = make_float2(c[mf][nf][half * 2 + 0], c[mf][nf][half * 2 + 1]);
                    *(float2*)(g_PQ + (size_t)n * 128 + col) = v;
                }
            }
        }
}

// ---------------------------------------------------------------------------
// Kernel 3: tf32 mma.sync edge GEMM — exact R9 (214us) version.
// TILE_M=128, 2 CTAs/SM, streams evict-first, indices prefetched pre-mainloop.
// ---------------------------------------------------------------------------
#define TILE_M 128
#define NTILES (N_EDGES / TILE_M)       // 6250
#define EDGE_GRID 296                   // 148 SMs x 2 CTAs

#define A_STRIDE 100                    // conflict-free frag loads
#define B_STRIDE 72
#define SMEM_A_OFF 0
#define SMEM_B_OFF (TILE_M * A_STRIDE)             // 12800 words
#define SMEM_BIAS_OFF (SMEM_B_OFF + 96 * B_STRIDE) // 19712 words
#define SMEM_WORDS (SMEM_BIAS_OFF + 64)            // 19776 words = 79104 B

__global__ void __launch_bounds__(256, 2) edge_kernel(
    const float* __restrict__ e_h, const float* __restrict__ ext,
    const int* __restrict__ src, const int* __restrict__ dst,
    float* __restrict__ out)
{
    extern __shared__ uint32_t smw[];
    uint32_t* As = smw + SMEM_A_OFF;
    uint32_t* Bs = smw + SMEM_B_OFF;
    float*  bias = (float*)(smw + SMEM_BIAS_OFF);

    int t = threadIdx.x;
    int wid = t >> 5;
    int lane = t & 31;
    int mw = wid >> 1;        // 0..3 -> M rows [mw*32, +32)
    int nw = wid & 1;         // 0..1 -> N cols [nw*32, +32)
    int lq = lane >> 2;       // 0..7
    int lr = lane & 3;        // 0..3

    // stage B (weights, tf32, [k][n] stride 72) + bias — once per CTA
    for (int i = t; i < 96 * 64; i += 256) {
        int k = i >> 6;
        int n = i & 63;
        Bs[k * B_STRIDE + n] = f2tf32(g_Wc[i]);
    }
    if (t < 64) bias[t] = g_bias[t];

    for (int tile = blockIdx.x; tile < NTILES; tile += EDGE_GRID) {
        int e0 = tile * TILE_M;
        __syncthreads();   // prev-iter LDS of As done (first iter: B/bias visible)

        // ---- stage A: e_h -> cols 0..63 (streaming load, cvt to tf32) ----
#pragma unroll
        for (int i = t; i < 2048; i += 256) {
            int m = i >> 4;
            int c4 = (i & 15) << 2;
            float4 v = __ldcs((const float4*)(e_h + (size_t)(e0 + m) * 64 + c4));
            uint4 w = make_uint4(f2tf32(v.x), f2tf32(v.y), f2tf32(v.z), f2tf32(v.w));
            *(uint4*)(As + m * A_STRIDE + c4) = w;
        }
        // ---- stage A: ext -> cols 64..95 ----
#pragma unroll
        for (int i = t; i < 1024; i += 256) {
            int m = i >> 3;
            int c4 = (i & 7) << 2;
            float4 v = __ldcs((const float4*)(ext + (size_t)(e0 + m) * 32 + c4));
            uint4 w = make_uint4(f2tf32(v.x), f2tf32(v.y), f2tf32(v.z), f2tf32(v.w));
            *(uint4*)(As + m * A_STRIDE + 64 + c4) = w;
        }

        // ---- prefetch gather indices for this thread's 4 edge rows ----
        int sv[2][2], dv[2][2];
#pragma unroll
        for (int mf = 0; mf < 2; mf++)
#pragma unroll
            for (int half = 0; half < 2; half++) {
                int e = e0 + mw * 32 + mf * 16 + half * 8 + lq;
                sv[mf][half] = src[e];
                dv[mf][half] = dst[e];
            }
        __syncthreads();

        // ---- mma mainloop: 12 K-steps of 8 ----
        float c[2][4][4];
#pragma unroll
        for (int mf = 0; mf < 2; mf++)
#pragma unroll
            for (int nf = 0; nf < 4; nf++)
#pragma unroll
                for (int i = 0; i < 4; i++) c[mf][nf][i] = 0.f;

#pragma unroll
        for (int ks = 0; ks < 12; ks++) {
            int kb = ks * 8;
            uint32_t a[2][4];
#pragma unroll
            for (int mf = 0; mf < 2; mf++) {
                const uint32_t* ap = As + (mw * 32 + mf * 16 + lq) * A_STRIDE + kb + lr;
                a[mf][0] = ap[0];
                a[mf][1] = ap[8 * A_STRIDE];
                a[mf][2] = ap[4];
                a[mf][3] = ap[8 * A_STRIDE + 4];
            }
            uint32_t b[4][2];
#pragma unroll
            for (int nf = 0; nf < 4; nf++) {
                const uint32_t* bp = Bs + (kb + lr) * B_STRIDE + nw * 32 + nf * 8 + lq;
                b[nf][0] = bp[0];
                b[nf][1] = bp[4 * B_STRIDE];
            }
#pragma unroll
            for (int mf = 0; mf < 2; mf++)
#pragma unroll
                for (int nf = 0; nf < 4; nf++)
                    mma_tf32(c[mf][nf], a[mf], b[nf]);
        }

        // ---- epilogue: +P[src] +Q[dst] +bias, ReLU, streaming store ----
#pragma unroll
        for (int mf = 0; mf < 2; mf++) {
#pragma unroll
            for (int half = 0; half < 2; half++) {
                int r = mw * 32 + mf * 16 + half * 8 + lq;
                int e = e0 + r;
                const float* P = g_PQ + (size_t)sv[mf][half] * 128;
                const float* Q = g_PQ + (size_t)dv[mf][half] * 128 + 64;
#pragma unroll
                for (int nf = 0; nf < 4; nf++) {
                    int col = nw * 32 + nf * 8 + 2 * lr;
                    float2 p = __ldg((const float2*)(P + col));
                    float2 q = __ldg((const float2*)(Q + col));
                    float2 bvv = *(const float2*)(bias + col);
                    float cx = c[mf][nf][half * 2 + 0];
                    float cy = c[mf][nf][half * 2 + 1];
                    float2 rv;
                    rv.x = fmaxf(cx + p.x + q.x + bvv.x, 0.f);
                    rv.y = fmaxf(cy + p.y + q.y + bvv.y, 0.f);
                    stg_cs(out + (size_t)e * 64 + col, rv);
                }
            }
        }
    }
}

// ---------------------------------------------------------------------------
extern "C" void kernel_launch(void* const* d_in, const int* in_sizes, int n_in,
                              void* d_out, int out_size) {
    const float* h   = (const float*)d_in[0];
    const float* e_h = (const float*)d_in[1];
    const float* ext = (const float*)d_in[2];
    const float* W1  = (const float*)d_in[3];
    const float* b1  = (const float*)d_in[4];
    const float* W2  = (const float*)d_in[5];
    const float* b2  = (const float*)d_in[6];
    const int*   src = (const int*)d_in[7];
    const int*   dst = (const int*)d_in[8];
    float* out = (float*)d_out;

    static bool attr_set = false;
    if (!attr_set) {
        cudaFuncSetAttribute(edge_kernel, cudaFuncAttributeMaxDynamicSharedMemorySize,
                             SMEM_WORDS * 4);
        cudaFuncSetAttribute(node_kernel, cudaFuncAttributeMaxDynamicSharedMemorySize,
                             NSM_WORDS * 4);
        attr_set = true;
    }

    prep_kernel<<<48, 256>>>(W1, b1, W2, b2);
    node_kernel<<<(N_NODES + 63) / 64, 256, NSM_WORDS * 4>>>(h);
    edge_kernel<<<EDGE_GRID, 256, SMEM_WORDS * 4>>>(e_h, ext, src, dst, out);
}

// round 12
// speedup vs baseline: 1.2079x; 1.0094x over previous
#include <cuda_runtime.h>
#include <cstdint>

#define N_NODES 50000
#define N_EDGES 800000

// ---- fused-weight / node-projection scratch (__device__ globals; no alloc) ----
// g_Wc / g_AD are stored PRE-ROUNDED to tf32 (rna) by prep_kernel, so all
// downstream staging is raw bit copies; mma reads top-19 bits directly.
__device__ float g_Wc[96 * 64];        // [k][n]: rows 0..63 = W1[64:128]@W2a, rows 64..95 = W2[64:96]
__device__ float g_AD[64 * 128];       // cols 0..63: A, cols 64..127: D
__device__ float g_bias[64];           // b1@W2a + b2 (full fp32)
__device__ float g_PQ[(size_t)N_NODES * 128];  // per-node: P (0..63), Q (64..127)

__device__ __forceinline__ uint32_t f2tf32(float x) {
    uint32_t r;
    asm("cvt.rna.tf32.f32 %0, %1;" : "=r"(r) : "f"(x));
    return r;
}
// streaming store (evict-first)
__device__ __forceinline__ void stg_cs(float* p, float2 v) {
    asm volatile("st.global.cs.v2.f32 [%0], {%1,%2};" :: "l"(p), "f"(v.x), "f"(v.y));
}
__device__ __forceinline__ void mma_tf32(float c[4], const uint32_t a[4], const uint32_t b[2]) {
    asm volatile(
        "mma.sync.aligned.m16n8k8.row.col.f32.tf32.tf32.f32 "
        "{%0,%1,%2,%3}, {%4,%5,%6,%7}, {%8,%9}, {%0,%1,%2,%3};"
        : "+f"(c[0]), "+f"(c[1]), "+f"(c[2]), "+f"(c[3])
        : "r"(a[0]), "r"(a[1]), "r"(a[2]), "r"(a[3]), "r"(b[0]), "r"(b[1]));
}

// ---------------------------------------------------------------------------
// Kernel 1: fuse weights; write g_AD / g_Wc PRE-ROUNDED to tf32 (rna).
// ---------------------------------------------------------------------------
__global__ void __launch_bounds__(256) prep_kernel(
    const float* __restrict__ W1, const float* __restrict__ b1,
    const float* __restrict__ W2, const float* __restrict__ b2) {
    __shared__ float W2s[64 * 64];
    int t = threadIdx.x;
    for (int i = t; i < 64 * 64; i += 256) W2s[i] = W2[i];
    __syncthreads();

    int o = blockIdx.x * 256 + t;   // 12288 = 192*64 exactly
    {
        int i = o >> 6;
        int j = o & 63;
        float s0 = 0.f, s1 = 0.f, s2 = 0.f, s3 = 0.f;
#pragma unroll
        for (int k = 0; k < 64; k += 4) {
            float4 w = *(const float4*)(W1 + i * 64 + k);
            s0 = fmaf(w.x, W2s[(k + 0) * 64 + j], s0);
            s1 = fmaf(w.y, W2s[(k + 1) * 64 + j], s1);
            s2 = fmaf(w.z, W2s[(k + 2) * 64 + j], s2);
            s3 = fmaf(w.w, W2s[(k + 3) * 64 + j], s3);
        }
        float s = __uint_as_float(f2tf32((s0 + s1) + (s2 + s3)));   // tf32-rounded
        if (i < 64)       g_AD[i * 128 + j] = s;                 // A
        else if (i < 128) g_Wc[(i - 64) * 64 + j] = s;           // B (e_h block)
        else              g_AD[(i - 128) * 128 + 64 + j] = s;    // D
    }
    if (blockIdx.x == 0) {
        for (int i = t; i < 32 * 64; i += 256)
            g_Wc[64 * 64 + i] = __uint_as_float(f2tf32(W2[64 * 64 + i]));  // ext block
        if (t < 64) {
            float s0 = 0.f, s1 = 0.f;
#pragma unroll
            for (int k = 0; k < 64; k += 2) {
                s0 = fmaf(b1[k], W2s[k * 64 + t], s0);
                s1 = fmaf(b1[k + 1], W2s[(k + 1) * 64 + t], s1);
            }
            g_bias[t] = s0 + s1 + b2[t];   // bias stays full fp32
        }
    }
}

// ---------------------------------------------------------------------------
// Kernel 2: node projections PQ = h @ [A|D] via tf32 mma.
// A (h) staged RAW fp32 bits (RZ-truncated by mma HW); B pre-rounded in prep.
// ---------------------------------------------------------------------------
#define NA_STRIDE 68                    // conflict-free A frags
#define NB_STRIDE 136                   // conflict-free B frags
#define NSM_A_OFF 0
#define NSM_B_OFF (64 * NA_STRIDE)      // 4352 words
#define NSM_WORDS (NSM_B_OFF + 64 * NB_STRIDE)   // 13056 words = 52224 B

__global__ void __launch_bounds__(256) node_kernel(const float* __restrict__ h) {
    extern __shared__ uint32_t nsm[];
    uint32_t* As = nsm + NSM_A_OFF;
    uint32_t* Bs = nsm + NSM_B_OFF;

    int t = threadIdx.x;
    int wid = t >> 5;
    int lane = t & 31;
    int mw = wid >> 2;        // 0..1 -> rows [mw*32, +32)
    int nw = wid & 3;         // 0..3 -> cols [nw*32, +32)
    int lq = lane >> 2;
    int lr = lane & 3;

    int n0 = blockIdx.x * 64;

    // stage B = g_AD (already tf32-rounded) -> raw copy, stride 136
#pragma unroll
    for (int j = 0; j < 8; j++) {
        int i = t + j * 256;
        int k = i >> 5;
        int c4 = (i & 31) << 2;
        *(uint4*)(Bs + k * NB_STRIDE + c4) = *(const uint4*)(g_AD + k * 128 + c4);
    }
    // stage A = h tile raw bits, stride 68 (clamp tail rows)
#pragma unroll
    for (int j = 0; j < 4; j++) {
        int i = t + j * 256;
        int m = i >> 4;
        int c4 = (i & 15) << 2;
        int n = n0 + m;
        if (n >= N_NODES) n = N_NODES - 1;
        *(uint4*)(As + m * NA_STRIDE + c4) = *(const uint4*)(h + (size_t)n * 64 + c4);
    }
    __syncthreads();

    float c[2][4][4];
#pragma unroll
    for (int mf = 0; mf < 2; mf++)
#pragma unroll
        for (int nf = 0; nf < 4; nf++)
#pragma unroll
            for (int i = 0; i < 4; i++) c[mf][nf][i] = 0.f;

#pragma unroll
    for (int ks = 0; ks < 8; ks++) {
        int kb = ks * 8;
        uint32_t a[2][4];
#pragma unroll
        for (int mf = 0; mf < 2; mf++) {
            const uint32_t* ap = As + (mw * 32 + mf * 16 + lq) * NA_STRIDE + kb + lr;
            a[mf][0] = ap[0];
            a[mf][1] = ap[8 * NA_STRIDE];
            a[mf][2] = ap[4];
            a[mf][3] = ap[8 * NA_STRIDE + 4];
        }
        uint32_t b[4][2];
#pragma unroll
        for (int nf = 0; nf < 4; nf++) {
            const uint32_t* bp = Bs + (kb + lr) * NB_STRIDE + nw * 32 + nf * 8 + lq;
            b[nf][0] = bp[0];
            b[nf][1] = bp[4 * NB_STRIDE];
        }
#pragma unroll
        for (int mf = 0; mf < 2; mf++)
#pragma unroll
            for (int nf = 0; nf < 4; nf++)
                mma_tf32(c[mf][nf], a[mf], b[nf]);
    }

    // store to g_PQ (predicated on node bound)
#pragma unroll
    for (int mf = 0; mf < 2; mf++)
#pragma unroll
        for (int half = 0; half < 2; half++) {
            int r = mw * 32 + mf * 16 + half * 8 + lq;
            int n = n0 + r;
            if (n < N_NODES) {
#pragma unroll
                for (int nf = 0; nf < 4; nf++) {
                    int col = nw * 32 + nf * 8 + 2 * lr;
                    float2 v = make_float2(c[mf][nf][half * 2 + 0], c[mf][nf][half * 2 + 1]);
                    *(float2*)(g_PQ + (size_t)n * 128 + col) = v;
                }
            }
        }
}

// ---------------------------------------------------------------------------
// Kernel 3: tf32 mma.sync edge GEMM (R9/R11 structure).
// A staged RAW fp32 bits (no per-element cvt); B pre-rounded in prep.
// Streams evict-first, indices prefetched pre-mainloop.
// ---------------------------------------------------------------------------
#define TILE_M 128
#define NTILES (N_EDGES / TILE_M)       // 6250
#define EDGE_GRID 296                   // 148 SMs x 2 CTAs

#define A_STRIDE 100                    // conflict-free frag loads
#define B_STRIDE 72
#define SMEM_A_OFF 0
#define SMEM_B_OFF (TILE_M * A_STRIDE)             // 12800 words
#define SMEM_BIAS_OFF (SMEM_B_OFF + 96 * B_STRIDE) // 19712 words
#define SMEM_WORDS (SMEM_BIAS_OFF + 64)            // 19776 words = 79104 B

__global__ void __launch_bounds__(256, 2) edge_kernel(
    const float* __restrict__ e_h, const float* __restrict__ ext,
    const int* __restrict__ src, const int* __restrict__ dst,
    float* __restrict__ out)
{
    extern __shared__ uint32_t smw[];
    uint32_t* As = smw + SMEM_A_OFF;
    uint32_t* Bs = smw + SMEM_B_OFF;
    float*  bias = (float*)(smw + SMEM_BIAS_OFF);

    int t = threadIdx.x;
    int wid = t >> 5;
    int lane = t & 31;
    int mw = wid >> 1;        // 0..3 -> M rows [mw*32, +32)
    int nw = wid & 1;         // 0..1 -> N cols [nw*32, +32)
    int lq = lane >> 2;       // 0..7
    int lr = lane & 3;        // 0..3

    // stage B (pre-rounded weights, raw copy, [k][n] stride 72) + bias — once
    for (int i = t; i < 96 * 64; i += 256) {
        int k = i >> 6;
        int n = i & 63;
        Bs[k * B_STRIDE + n] = __float_as_uint(g_Wc[i]);
    }
    if (t < 64) bias[t] = g_bias[t];

    for (int tile = blockIdx.x; tile < NTILES; tile += EDGE_GRID) {
        int e0 = tile * TILE_M;
        __syncthreads();   // prev-iter LDS of As done (first iter: B/bias visible)

        // ---- stage A: e_h -> cols 0..63 (streaming load, RAW bits) ----
#pragma unroll
        for (int i = t; i < 2048; i += 256) {
            int m = i >> 4;
            int c4 = (i & 15) << 2;
            uint4 v = __ldcs((const uint4*)(e_h + (size_t)(e0 + m) * 64 + c4));
            *(uint4*)(As + m * A_STRIDE + c4) = v;
        }
        // ---- stage A: ext -> cols 64..95 ----
#pragma unroll
        for (int i = t; i < 1024; i += 256) {
            int m = i >> 3;
            int c4 = (i & 7) << 2;
            uint4 v = __ldcs((const uint4*)(ext + (size_t)(e0 + m) * 32 + c4));
            *(uint4*)(As + m * A_STRIDE + 64 + c4) = v;
        }

        // ---- prefetch gather indices for this thread's 4 edge rows ----
        int sv[2][2], dv[2][2];
#pragma unroll
        for (int mf = 0; mf < 2; mf++)
#pragma unroll
            for (int half = 0; half < 2; half++) {
                int e = e0 + mw * 32 + mf * 16 + half * 8 + lq;
                sv[mf][half] = src[e];
                dv[mf][half] = dst[e];
            }
        __syncthreads();

        // ---- mma mainloop: 12 K-steps of 8 ----
        float c[2][4][4];
#pragma unroll
        for (int mf = 0; mf < 2; mf++)
#pragma unroll
            for (int nf = 0; nf < 4; nf++)
#pragma unroll
                for (int i = 0; i < 4; i++) c[mf][nf][i] = 0.f;

#pragma unroll
        for (int ks = 0; ks < 12; ks++) {
            int kb = ks * 8;
            uint32_t a[2][4];
#pragma unroll
            for (int mf = 0; mf < 2; mf++) {
                const uint32_t* ap = As + (mw * 32 + mf * 16 + lq) * A_STRIDE + kb + lr;
                a[mf][0] = ap[0];
                a[mf][1] = ap[8 * A_STRIDE];
                a[mf][2] = ap[4];
                a[mf][3] = ap[8 * A_STRIDE + 4];
            }
            uint32_t b[4][2];
#pragma unroll
            for (int nf = 0; nf < 4; nf++) {
                const uint32_t* bp = Bs + (kb + lr) * B_STRIDE + nw * 32 + nf * 8 + lq;
                b[nf][0] = bp[0];
                b[nf][1] = bp[4 * B_STRIDE];
            }
#pragma unroll
            for (int mf = 0; mf < 2; mf++)
#pragma unroll
                for (int nf = 0; nf < 4; nf++)
                    mma_tf32(c[mf][nf], a[mf], b[nf]);
        }

        // ---- epilogue: +P[src] +Q[dst] +bias, ReLU, streaming store ----
#pragma unroll
        for (int mf = 0; mf < 2; mf++) {
#pragma unroll
            for (int half = 0; half < 2; half++) {
                int r = mw * 32 + mf * 16 + half * 8 + lq;
                int e = e0 + r;
                const float* P = g_PQ + (size_t)sv[mf][half] * 128;
                const float* Q = g_PQ + (size_t)dv[mf][half] * 128 + 64;
#pragma unroll
                for (int nf = 0; nf < 4; nf++) {
                    int col = nw * 32 + nf * 8 + 2 * lr;
                    float2 p = __ldg((const float2*)(P + col));
                    float2 q = __ldg((const float2*)(Q + col));
                    float2 bvv = *(const float2*)(bias + col);
                    float cx = c[mf][nf][half * 2 + 0];
                    float cy = c[mf][nf][half * 2 + 1];
                    float2 rv;
                    rv.x = fmaxf(cx + p.x + q.x + bvv.x, 0.f);
                    rv.y = fmaxf(cy + p.y + q.y + bvv.y, 0.f);
                    stg_cs(out + (size_t)e * 64 + col, rv);
                }
            }
        }
    }
}

// ---------------------------------------------------------------------------
extern "C" void kernel_launch(void* const* d_in, const int* in_sizes, int n_in,
                              void* d_out, int out_size) {
    const float* h   = (const float*)d_in[0];
    const float* e_h = (const float*)d_in[1];
    const float* ext = (const float*)d_in[2];
    const float* W1  = (const float*)d_in[3];
    const float* b1  = (const float*)d_in[4];
    const float* W2  = (const float*)d_in[5];
    const float* b2  = (const float*)d_in[6];
    const int*   src = (const int*)d_in[7];
    const int*   dst = (const int*)d_in[8];
    float* out = (float*)d_out;

    static bool attr_set = false;
    if (!attr_set) {
        cudaFuncSetAttribute(edge_kernel, cudaFuncAttributeMaxDynamicSharedMemorySize,
                             SMEM_WORDS * 4);
        cudaFuncSetAttribute(node_kernel, cudaFuncAttributeMaxDynamicSharedMemorySize,
                             NSM_WORDS * 4);
        attr_set = true;
    }

    prep_kernel<<<48, 256>>>(W1, b1, W2, b2);
    node_kernel<<<(N_NODES + 63) / 64, 256, NSM_WORDS * 4>>>(h);
    edge_kernel<<<EDGE_GRID, 256, SMEM_WORDS * 4>>>(e_h, ext, src, dst, out);
}

// round 13
// speedup vs baseline: 1.4199x; 1.1754x over previous
#include <cuda_runtime.h>
#include <cuda_fp16.h>
#include <cstdint>

#define N_NODES 50000
#define N_EDGES 800000

// ---- scratch (__device__ globals; no alloc) ----
// Weight matrices pre-rounded to fp16 by prep, in [n][k] layout for direct
// raw-copy into the mma B operand. Bias and PQ stay fp32.
__device__ __half g_Wch[64 * 96];      // edge B: [n][k], k 0..63 = e_h block, 64..95 = ext block
__device__ __half g_ADh[128 * 64];     // node B: [n][k], n 0..63 = A cols(P), 64..127 = D cols(Q)
__device__ float  g_bias[64];          // b1@W2a + b2 (fp32)
__device__ float  g_PQ[(size_t)N_NODES * 128];  // per-node: P (0..63), Q (64..127)

// pack two fp32 -> fp16x2 (lo = first arg, RNE)
__device__ __forceinline__ uint32_t f2h2(float lo, float hi) {
    uint32_t r;
    asm("cvt.rn.f16x2.f32 %0, %1, %2;" : "=r"(r) : "f"(hi), "f"(lo));
    return r;
}
// streaming store (evict-first)
__device__ __forceinline__ void stg_cs(float* p, float2 v) {
    asm volatile("st.global.cs.v2.f32 [%0], {%1,%2};" :: "l"(p), "f"(v.x), "f"(v.y));
}
__device__ __forceinline__ void mma_f16(float c[4], const uint32_t a[4], const uint32_t b[2]) {
    asm volatile(
        "mma.sync.aligned.m16n8k16.row.col.f32.f16.f16.f32 "
        "{%0,%1,%2,%3}, {%4,%5,%6,%7}, {%8,%9}, {%0,%1,%2,%3};"
        : "+f"(c[0]), "+f"(c[1]), "+f"(c[2]), "+f"(c[3])
        : "r"(a[0]), "r"(a[1]), "r"(a[2]), "r"(a[3]), "r"(b[0]), "r"(b[1]));
}

// ---------------------------------------------------------------------------
// Kernel 1: fuse weights; emit fp16 [n][k] weight arrays + fp32 bias.
// ---------------------------------------------------------------------------
__global__ void __launch_bounds__(256) prep_kernel(
    const float* __restrict__ W1, const float* __restrict__ b1,
    const float* __restrict__ W2, const float* __restrict__ b2) {
    __shared__ float W2s[64 * 64];
    int t = threadIdx.x;
    for (int i = t; i < 64 * 64; i += 256) W2s[i] = W2[i];
    __syncthreads();

    int o = blockIdx.x * 256 + t;   // 12288 = 192*64 exactly
    {
        int i = o >> 6;
        int j = o & 63;
        float s0 = 0.f, s1 = 0.f, s2 = 0.f, s3 = 0.f;
#pragma unroll
        for (int k = 0; k < 64; k += 4) {
            float4 w = *(const float4*)(W1 + i * 64 + k);
            s0 = fmaf(w.x, W2s[(k + 0) * 64 + j], s0);
            s1 = fmaf(w.y, W2s[(k + 1) * 64 + j], s1);
            s2 = fmaf(w.z, W2s[(k + 2) * 64 + j], s2);
            s3 = fmaf(w.w, W2s[(k + 3) * 64 + j], s3);
        }
        __half hs = __float2half_rn((s0 + s1) + (s2 + s3));
        if (i < 64)       g_ADh[j * 64 + i] = hs;                  // A block: node B[n=j][k=i]
        else if (i < 128) g_Wch[j * 96 + (i - 64)] = hs;           // e_h block: edge B[n=j][k=i-64]
        else              g_ADh[(64 + j) * 64 + (i - 128)] = hs;   // D block: node B[n=64+j][k=i-128]
    }
    if (blockIdx.x == 0) {
        // ext block: edge B[n][64+k'] = W2[64+k'][n]
        for (int idx = t; idx < 32 * 64; idx += 256) {
            int kp = idx >> 6;
            int n = idx & 63;
            g_Wch[n * 96 + 64 + kp] = __float2half_rn(W2[(64 + kp) * 64 + n]);
        }
        if (t < 64) {
            float s0 = 0.f, s1 = 0.f;
#pragma unroll
            for (int k = 0; k < 64; k += 2) {
                s0 = fmaf(b1[k], W2s[k * 64 + t], s0);
                s1 = fmaf(b1[k + 1], W2s[(k + 1) * 64 + t], s1);
            }
            g_bias[t] = s0 + s1 + b2[t];
        }
    }
}

// ---------------------------------------------------------------------------
// Kernel 2: node projections PQ = h @ [A|D] via fp16 m16n8k16 mma.
// 8 warps = 2 M-groups x 4 N-groups over 64x128; K=64 -> 4 K-steps.
// SMEM word strides == 4 (mod 32) -> conflict-free frag loads.
// ---------------------------------------------------------------------------
#define NA_W 36                         // words/row for A (64 halves = 32 w + pad)
#define NB_W 36                         // words/row for B
#define NSM_A_OFF 0
#define NSM_B_OFF (64 * NA_W)           // 2304 words
#define NSM_WORDS (NSM_B_OFF + 128 * NB_W)   // 6912 words = 27648 B

__global__ void __launch_bounds__(256) node_kernel(const float* __restrict__ h) {
    extern __shared__ uint32_t nsm[];
    uint32_t* As = nsm + NSM_A_OFF;
    uint32_t* Bs = nsm + NSM_B_OFF;

    int t = threadIdx.x;
    int wid = t >> 5;
    int lane = t & 31;
    int mw = wid >> 2;        // 0..1 -> rows [mw*32, +32)
    int nw = wid & 3;         // 0..3 -> cols [nw*32, +32)
    int lq = lane >> 2;
    int lr = lane & 3;

    int n0 = blockIdx.x * 64;

    // stage B = g_ADh raw copy: 128 rows x 32 words -> stride 36 (4 uint4/thread)
#pragma unroll
    for (int j = 0; j < 4; j++) {
        int i = t + j * 256;            // uint4 index, 1024 total (8/row)
        int r = i >> 3;
        int c4 = (i & 7) << 2;
        *(uint4*)(Bs + r * NB_W + c4) = *(const uint4*)((const uint32_t*)g_ADh + r * 32 + c4);
    }
    // stage A = h tile fp32 -> fp16 (clamp tail rows): 4 float4/thread
#pragma unroll
    for (int j = 0; j < 4; j++) {
        int i = t + j * 256;            // 1024 float4 units
        int m = i >> 4;
        int c4 = (i & 15) << 2;         // fp32 col
        int n = n0 + m;
        if (n >= N_NODES) n = N_NODES - 1;
        float4 v = *(const float4*)(h + (size_t)n * 64 + c4);
        uint2 w = make_uint2(f2h2(v.x, v.y), f2h2(v.z, v.w));
        *(uint2*)(As + m * NA_W + (c4 >> 1)) = w;
    }
    __syncthreads();

    float c[2][4][4];
#pragma unroll
    for (int mf = 0; mf < 2; mf++)
#pragma unroll
        for (int nf = 0; nf < 4; nf++)
#pragma unroll
            for (int i = 0; i < 4; i++) c[mf][nf][i] = 0.f;

#pragma unroll
    for (int ks = 0; ks < 4; ks++) {    // K=64, 16 per step -> 8 words per step
        int kw = ks * 8;
        uint32_t a[2][4];
#pragma unroll
        for (int mf = 0; mf < 2; mf++) {
            const uint32_t* ap = As + (mw * 32 + mf * 16 + lq) * NA_W + kw + lr;
            a[mf][0] = ap[0];
            a[mf][1] = ap[8 * NA_W];
            a[mf][2] = ap[4];
            a[mf][3] = ap[8 * NA_W + 4];
        }
        uint32_t b[4][2];
#pragma unroll
        for (int nf = 0; nf < 4; nf++) {
            const uint32_t* bp = Bs + (nw * 32 + nf * 8 + lq) * NB_W + kw + lr;
            b[nf][0] = bp[0];
            b[nf][1] = bp[4];
        }
#pragma unroll
        for (int mf = 0; mf < 2; mf++)
#pragma unroll
            for (int nf = 0; nf < 4; nf++)
                mma_f16(c[mf][nf], a[mf], b[nf]);
    }

    // store to g_PQ (predicated on node bound)
#pragma unroll
    for (int mf = 0; mf < 2; mf++)
#pragma unroll
        for (int half = 0; half < 2; half++) {
            int r = mw * 32 + mf * 16 + half * 8 + lq;
            int n = n0 + r;
            if (n < N_NODES) {
#pragma unroll
                for (int nf = 0; nf < 4; nf++) {
                    int col = nw * 32 + nf * 8 + 2 * lr;
                    float2 v = make_float2(c[mf][nf][half * 2 + 0], c[mf][nf][half * 2 + 1]);
                    *(float2*)(g_PQ + (size_t)n * 128 + col) = v;
                }
            }
        }
}

// ---------------------------------------------------------------------------
// Kernel 3: fp16 m16n8k16 edge GEMM (R9/R11 structure, half the inner loop).
// TILE_M=128, 2 CTAs/SM, streams evict-first, indices prefetched pre-mainloop.
// ---------------------------------------------------------------------------
#define TILE_M 128
#define NTILES (N_EDGES / TILE_M)       // 6250
#define EDGE_GRID 296                   // 148 SMs x 2 CTAs

#define EA_W 52                         // words/row for A (96 halves = 48 w + pad); 52%32=20 -> conflict-free
#define EB_W 52                         // words/row for B (96 halves = 48 w + pad)
#define SMEM_A_OFF 0
#define SMEM_B_OFF (TILE_M * EA_W)                 // 6656 words
#define SMEM_BIAS_OFF (SMEM_B_OFF + 64 * EB_W)     // 9984 words
#define SMEM_WORDS (SMEM_BIAS_OFF + 64)            // 10048 words = 40192 B

__global__ void __launch_bounds__(256, 2) edge_kernel(
    const float* __restrict__ e_h, const float* __restrict__ ext,
    const int* __restrict__ src, const int* __restrict__ dst,
    float* __restrict__ out)
{
    extern __shared__ uint32_t smw[];
    uint32_t* As = smw + SMEM_A_OFF;
    uint32_t* Bs = smw + SMEM_B_OFF;
    float*  bias = (float*)(smw + SMEM_BIAS_OFF);

    int t = threadIdx.x;
    int wid = t >> 5;
    int lane = t & 31;
    int mw = wid >> 1;        // 0..3 -> M rows [mw*32, +32)
    int nw = wid & 1;         // 0..1 -> N cols [nw*32, +32)
    int lq = lane >> 2;       // 0..7
    int lr = lane & 3;        // 0..3

    // stage B = g_Wch raw copy: 64 rows x 12 uint4 -> stride 52 words
    {
#pragma unroll
        for (int j = 0; j < 4; j++) {
            int i = t + j * 256;        // 0..1023, 16 slots/row, 12 valid
            int r = i >> 4;
            int s = i & 15;
            if (s < 12)
                *(uint4*)(Bs + r * EB_W + s * 4) =
                    *(const uint4*)((const uint32_t*)g_Wch + r * 48 + s * 4);
        }
    }
    if (t < 64) bias[t] = g_bias[t];

    for (int tile = blockIdx.x; tile < NTILES; tile += EDGE_GRID) {
        int e0 = tile * TILE_M;
        __syncthreads();   // prev-iter LDS of As done (first iter: B/bias visible)

        // ---- stage A: e_h -> k 0..63 (words 0..31), streaming, cvt fp16 ----
#pragma unroll
        for (int i = t; i < 2048; i += 256) {
            int m = i >> 4;
            int c4 = (i & 15) << 2;     // fp32 col
            float4 v = __ldcs((const float4*)(e_h + (size_t)(e0 + m) * 64 + c4));
            uint2 w = make_uint2(f2h2(v.x, v.y), f2h2(v.z, v.w));
            *(uint2*)(As + m * EA_W + (c4 >> 1)) = w;
        }
        // ---- stage A: ext -> k 64..95 (words 32..47) ----
#pragma unroll
        for (int i = t; i < 1024; i += 256) {
            int m = i >> 3;
            int c4 = (i & 7) << 2;
            float4 v = __ldcs((const float4*)(ext + (size_t)(e0 + m) * 32 + c4));
            uint2 w = make_uint2(f2h2(v.x, v.y), f2h2(v.z, v.w));
            *(uint2*)(As + m * EA_W + 32 + (c4 >> 1)) = w;
        }

        // ---- prefetch gather indices for this thread's 4 edge rows ----
        int sv[2][2], dv[2][2];
#pragma unroll
        for (int mf = 0; mf < 2; mf++)
#pragma unroll
            for (int half = 0; half < 2; half++) {
                int e = e0 + mw * 32 + mf * 16 + half * 8 + lq;
                sv[mf][half] = src[e];
                dv[mf][half] = dst[e];
            }
        __syncthreads();

        // ---- mma mainloop: 6 K-steps of 16 ----
        float c[2][4][4];
#pragma unroll
        for (int mf = 0; mf < 2; mf++)
#pragma unroll
            for (int nf = 0; nf < 4; nf++)
#pragma unroll
                for (int i = 0; i < 4; i++) c[mf][nf][i] = 0.f;

#pragma unroll
        for (int ks = 0; ks < 6; ks++) {
            int kw = ks * 8;
            uint32_t a[2][4];
#pragma unroll
            for (int mf = 0; mf < 2; mf++) {
                const uint32_t* ap = As + (mw * 32 + mf * 16 + lq) * EA_W + kw + lr;
                a[mf][0] = ap[0];
                a[mf][1] = ap[8 * EA_W];
                a[mf][2] = ap[4];
                a[mf][3] = ap[8 * EA_W + 4];
            }
            uint32_t b[4][2];
#pragma unroll
            for (int nf = 0; nf < 4; nf++) {
                const uint32_t* bp = Bs + (nw * 32 + nf * 8 + lq) * EB_W + kw + lr;
                b[nf][0] = bp[0];
                b[nf][1] = bp[4];
            }
#pragma unroll
            for (int mf = 0; mf < 2; mf++)
#pragma unroll
                for (int nf = 0; nf < 4; nf++)
                    mma_f16(c[mf][nf], a[mf], b[nf]);
        }

        // ---- epilogue: +P[src] +Q[dst] +bias, ReLU, streaming store ----
#pragma unroll
        for (int mf = 0; mf < 2; mf++) {
#pragma unroll
            for (int half = 0; half < 2; half++) {
                int r = mw * 32 + mf * 16 + half * 8 + lq;
                int e = e0 + r;
                const float* P = g_PQ + (size_t)sv[mf][half] * 128;
                const float* Q = g_PQ + (size_t)dv[mf][half] * 128 + 64;
#pragma unroll
                for (int nf = 0; nf < 4; nf++) {
                    int col = nw * 32 + nf * 8 + 2 * lr;
                    float2 p = __ldg((const float2*)(P + col));
                    float2 q = __ldg((const float2*)(Q + col));
                    float2 bvv = *(const float2*)(bias + col);
                    float cx = c[mf][nf][half * 2 + 0];
                    float cy = c[mf][nf][half * 2 + 1];
                    float2 rv;
                    rv.x = fmaxf(cx + p.x + q.x + bvv.x, 0.f);
                    rv.y = fmaxf(cy + p.y + q.y + bvv.y, 0.f);
                    stg_cs(out + (size_t)e * 64 + col, rv);
                }
            }
        }
    }
}

// ---------------------------------------------------------------------------
extern "C" void kernel_launch(void* const* d_in, const int* in_sizes, int n_in,
                              void* d_out, int out_size) {
    const float* h   = (const float*)d_in[0];
    const float* e_h = (const float*)d_in[1];
    const float* ext = (const float*)d_in[2];
    const float* W1  = (const float*)d_in[3];
    const float* b1  = (const float*)d_in[4];
    const float* W2  = (const float*)d_in[5];
    const float* b2  = (const float*)d_in[6];
    const int*   src = (const int*)d_in[7];
    const int*   dst = (const int*)d_in[8];
    float* out = (float*)d_out;

    static bool attr_set = false;
    if (!attr_set) {
        cudaFuncSetAttribute(edge_kernel, cudaFuncAttributeMaxDynamicSharedMemorySize,
                             SMEM_WORDS * 4);
        cudaFuncSetAttribute(node_kernel, cudaFuncAttributeMaxDynamicSharedMemorySize,
                             NSM_WORDS * 4);
        attr_set = true;
    }

    prep_kernel<<<48, 256>>>(W1, b1, W2, b2);
    node_kernel<<<(N_NODES + 63) / 64, 256, NSM_WORDS * 4>>>(h);
    edge_kernel<<<EDGE_GRID, 256, SMEM_WORDS * 4>>>(e_h, ext, src, dst, out);
}

// round 14
// speedup vs baseline: 1.5136x; 1.0660x over previous
#include <cuda_runtime.h>
#include <cuda_fp16.h>
#include <cstdint>

#define N_NODES 50000
#define N_EDGES 800000

// ---- scratch (__device__ globals; no alloc) ----
__device__ __half g_Wch[64 * 96];      // edge B: [n][k], k 0..63 = e_h block, 64..95 = ext block
__device__ __half g_ADh[128 * 64];     // node B: [n][k], n 0..63 = A cols(P), 64..127 = D cols(Q)
__device__ float  g_bias[64];          // b1@W2a + b2 (fp32)
__device__ float  g_PQ[(size_t)N_NODES * 128];  // per-node: P (0..63), Q (64..127)

__device__ __forceinline__ uint32_t f2h2(float lo, float hi) {
    uint32_t r;
    asm("cvt.rn.f16x2.f32 %0, %1, %2;" : "=r"(r) : "f"(hi), "f"(lo));
    return r;
}
__device__ __forceinline__ void stg_cs(float* p, float2 v) {
    asm volatile("st.global.cs.v2.f32 [%0], {%1,%2};" :: "l"(p), "f"(v.x), "f"(v.y));
}
__device__ __forceinline__ void mma_f16(float c[4], const uint32_t a[4], const uint32_t b[2]) {
    asm volatile(
        "mma.sync.aligned.m16n8k16.row.col.f32.f16.f16.f32 "
        "{%0,%1,%2,%3}, {%4,%5,%6,%7}, {%8,%9}, {%0,%1,%2,%3};"
        : "+f"(c[0]), "+f"(c[1]), "+f"(c[2]), "+f"(c[3])
        : "r"(a[0]), "r"(a[1]), "r"(a[2]), "r"(a[3]), "r"(b[0]), "r"(b[1]));
}
__device__ __forceinline__ void ldsm_x4(uint32_t& r0, uint32_t& r1, uint32_t& r2, uint32_t& r3,
                                        uint32_t addr) {
    asm volatile("ldmatrix.sync.aligned.m8n8.x4.shared.b16 {%0,%1,%2,%3}, [%4];"
                 : "=r"(r0), "=r"(r1), "=r"(r2), "=r"(r3) : "r"(addr));
}
__device__ __forceinline__ uint32_t smem_u32(const void* p) {
    return (uint32_t)__cvta_generic_to_shared(p);
}

// ---------------------------------------------------------------------------
// Kernel 1: fuse weights; emit fp16 [n][k] weight arrays + fp32 bias.
// ---------------------------------------------------------------------------
__global__ void __launch_bounds__(256) prep_kernel(
    const float* __restrict__ W1, const float* __restrict__ b1,
    const float* __restrict__ W2, const float* __restrict__ b2) {
    __shared__ float W2s[64 * 64];
    int t = threadIdx.x;
    for (int i = t; i < 64 * 64; i += 256) W2s[i] = W2[i];
    __syncthreads();

    int o = blockIdx.x * 256 + t;   // 12288 = 192*64 exactly
    {
        int i = o >> 6;
        int j = o & 63;
        float s0 = 0.f, s1 = 0.f, s2 = 0.f, s3 = 0.f;
#pragma unroll
        for (int k = 0; k < 64; k += 4) {
            float4 w = *(const float4*)(W1 + i * 64 + k);
            s0 = fmaf(w.x, W2s[(k + 0) * 64 + j], s0);
            s1 = fmaf(w.y, W2s[(k + 1) * 64 + j], s1);
            s2 = fmaf(w.z, W2s[(k + 2) * 64 + j], s2);
            s3 = fmaf(w.w, W2s[(k + 3) * 64 + j], s3);
        }
        __half hs = __float2half_rn((s0 + s1) + (s2 + s3));
        if (i < 64)       g_ADh[j * 64 + i] = hs;                  // A block: node B[n=j][k=i]
        else if (i < 128) g_Wch[j * 96 + (i - 64)] = hs;           // e_h block: edge B[n=j][k=i-64]
        else              g_ADh[(64 + j) * 64 + (i - 128)] = hs;   // D block
    }
    if (blockIdx.x == 0) {
        for (int idx = t; idx < 32 * 64; idx += 256) {
            int kp = idx >> 6;
            int n = idx & 63;
            g_Wch[n * 96 + 64 + kp] = __float2half_rn(W2[(64 + kp) * 64 + n]);
        }
        if (t < 64) {
            float s0 = 0.f, s1 = 0.f;
#pragma unroll
            for (int k = 0; k < 64; k += 2) {
                s0 = fmaf(b1[k], W2s[k * 64 + t], s0);
                s1 = fmaf(b1[k + 1], W2s[(k + 1) * 64 + t], s1);
            }
            g_bias[t] = s0 + s1 + b2[t];
        }
    }
}

// ---------------------------------------------------------------------------
// Kernel 2: node projections PQ = h @ [A|D] via fp16 m16n8k16 mma (R13).
// ---------------------------------------------------------------------------
#define NA_W 36
#define NB_W 36
#define NSM_A_OFF 0
#define NSM_B_OFF (64 * NA_W)           // 2304 words
#define NSM_WORDS (NSM_B_OFF + 128 * NB_W)   // 6912 words = 27648 B

__global__ void __launch_bounds__(256) node_kernel(const float* __restrict__ h) {
    extern __shared__ uint32_t nsm[];
    uint32_t* As = nsm + NSM_A_OFF;
    uint32_t* Bs = nsm + NSM_B_OFF;

    int t = threadIdx.x;
    int wid = t >> 5;
    int lane = t & 31;
    int mw = wid >> 2;
    int nw = wid & 3;
    int lq = lane >> 2;
    int lr = lane & 3;

    int n0 = blockIdx.x * 64;

#pragma unroll
    for (int j = 0; j < 4; j++) {
        int i = t + j * 256;
        int r = i >> 3;
        int c4 = (i & 7) << 2;
        *(uint4*)(Bs + r * NB_W + c4) = *(const uint4*)((const uint32_t*)g_ADh + r * 32 + c4);
    }
#pragma unroll
    for (int j = 0; j < 4; j++) {
        int i = t + j * 256;
        int m = i >> 4;
        int c4 = (i & 15) << 2;
        int n = n0 + m;
        if (n >= N_NODES) n = N_NODES - 1;
        float4 v = *(const float4*)(h + (size_t)n * 64 + c4);
        uint2 w = make_uint2(f2h2(v.x, v.y), f2h2(v.z, v.w));
        *(uint2*)(As + m * NA_W + (c4 >> 1)) = w;
    }
    __syncthreads();

    float c[2][4][4];
#pragma unroll
    for (int mf = 0; mf < 2; mf++)
#pragma unroll
        for (int nf = 0; nf < 4; nf++)
#pragma unroll
            for (int i = 0; i < 4; i++) c[mf][nf][i] = 0.f;

#pragma unroll
    for (int ks = 0; ks < 4; ks++) {
        int kw = ks * 8;
        uint32_t a[2][4];
#pragma unroll
        for (int mf = 0; mf < 2; mf++) {
            const uint32_t* ap = As + (mw * 32 + mf * 16 + lq) * NA_W + kw + lr;
            a[mf][0] = ap[0];
            a[mf][1] = ap[8 * NA_W];
            a[mf][2] = ap[4];
            a[mf][3] = ap[8 * NA_W + 4];
        }
        uint32_t b[4][2];
#pragma unroll
        for (int nf = 0; nf < 4; nf++) {
            const uint32_t* bp = Bs + (nw * 32 + nf * 8 + lq) * NB_W + kw + lr;
            b[nf][0] = bp[0];
            b[nf][1] = bp[4];
        }
#pragma unroll
        for (int mf = 0; mf < 2; mf++)
#pragma unroll
            for (int nf = 0; nf < 4; nf++)
                mma_f16(c[mf][nf], a[mf], b[nf]);
    }

#pragma unroll
    for (int mf = 0; mf < 2; mf++)
#pragma unroll
        for (int half = 0; half < 2; half++) {
            int r = mw * 32 + mf * 16 + half * 8 + lq;
            int n = n0 + r;
            if (n < N_NODES) {
#pragma unroll
                for (int nf = 0; nf < 4; nf++) {
                    int col = nw * 32 + nf * 8 + 2 * lr;
                    float2 v = make_float2(c[mf][nf][half * 2 + 0], c[mf][nf][half * 2 + 1]);
                    *(float2*)(g_PQ + (size_t)n * 128 + col) = v;
                }
            }
        }
}

// ---------------------------------------------------------------------------
// Kernel 3: fp16 m16n8k16 edge GEMM + ldmatrix frag loads (24 LDSM vs 96 LDS).
// TILE_M=128, 2 CTAs/SM, streams evict-first, indices prefetched pre-mainloop.
// ---------------------------------------------------------------------------
#define TILE_M 128
#define NTILES (N_EDGES / TILE_M)       // 6250
#define EDGE_GRID 296                   // 148 SMs x 2 CTAs

#define EA_W 52                         // words/row (96 halves = 48 w + pad); rows hit distinct banks
#define EB_W 52
#define SMEM_A_OFF 0
#define SMEM_B_OFF (TILE_M * EA_W)                 // 6656 words
#define SMEM_BIAS_OFF (SMEM_B_OFF + 64 * EB_W)     // 9984 words
#define SMEM_WORDS (SMEM_BIAS_OFF + 64)            // 10048 words = 40192 B

__global__ void __launch_bounds__(256, 2) edge_kernel(
    const float* __restrict__ e_h, const float* __restrict__ ext,
    const int* __restrict__ src, const int* __restrict__ dst,
    float* __restrict__ out)
{
    extern __shared__ uint32_t smw[];
    uint32_t* As = smw + SMEM_A_OFF;
    uint32_t* Bs = smw + SMEM_B_OFF;
    float*  bias = (float*)(smw + SMEM_BIAS_OFF);

    int t = threadIdx.x;
    int wid = t >> 5;
    int lane = t & 31;
    int mw = wid >> 1;        // 0..3 -> M rows [mw*32, +32)
    int nw = wid & 1;         // 0..1 -> N cols [nw*32, +32)
    int lq = lane >> 2;       // 0..7
    int lr = lane & 3;        // 0..3

    // stage B = g_Wch raw copy: 64 rows x 12 uint4 -> stride 52 words
#pragma unroll
    for (int j = 0; j < 4; j++) {
        int i = t + j * 256;
        int r = i >> 4;
        int s = i & 15;
        if (s < 12)
            *(uint4*)(Bs + r * EB_W + s * 4) =
                *(const uint4*)((const uint32_t*)g_Wch + r * 48 + s * 4);
    }
    if (t < 64) bias[t] = g_bias[t];

    // ldmatrix lane base addresses (bytes).
    // A x4 per (ks,mf): matrices = (rows 0-7,klo),(rows 8-15,klo),(rows 0-7,khi),(rows 8-15,khi)
    // B x4 per (ks,pair): matrices = (nf even,klo),(nf even,khi),(nf odd,klo),(nf odd,khi)
    int g8 = lane >> 3;       // 0..3 lane group
    int l8 = lane & 7;
    uint32_t aAddr = smem_u32(As) +
        (((mw * 32 + ((g8 & 1) ? 8 : 0) + l8) * EA_W) + ((g8 >> 1) * 4)) * 4;
    uint32_t bAddr = smem_u32(Bs) +
        (((nw * 32 + ((g8 >> 1) ? 8 : 0) + l8) * EB_W) + ((g8 & 1) * 4)) * 4;

    for (int tile = blockIdx.x; tile < NTILES; tile += EDGE_GRID) {
        int e0 = tile * TILE_M;
        __syncthreads();   // prev-iter LDS of As done (first iter: B/bias visible)

        // ---- stage A: e_h -> k 0..63 (words 0..31), streaming, cvt fp16 ----
#pragma unroll
        for (int i = t; i < 2048; i += 256) {
            int m = i >> 4;
            int c4 = (i & 15) << 2;
            float4 v = __ldcs((const float4*)(e_h + (size_t)(e0 + m) * 64 + c4));
            uint2 w = make_uint2(f2h2(v.x, v.y), f2h2(v.z, v.w));
            *(uint2*)(As + m * EA_W + (c4 >> 1)) = w;
        }
        // ---- stage A: ext -> k 64..95 (words 32..47) ----
#pragma unroll
        for (int i = t; i < 1024; i += 256) {
            int m = i >> 3;
            int c4 = (i & 7) << 2;
            float4 v = __ldcs((const float4*)(ext + (size_t)(e0 + m) * 32 + c4));
            uint2 w = make_uint2(f2h2(v.x, v.y), f2h2(v.z, v.w));
            *(uint2*)(As + m * EA_W + 32 + (c4 >> 1)) = w;
        }

        // ---- prefetch gather indices for this thread's 4 edge rows ----
        int sv[2][2], dv[2][2];
#pragma unroll
        for (int mf = 0; mf < 2; mf++)
#pragma unroll
            for (int half = 0; half < 2; half++) {
                int e = e0 + mw * 32 + mf * 16 + half * 8 + lq;
                sv[mf][half] = src[e];
                dv[mf][half] = dst[e];
            }
        __syncthreads();

        // ---- mma mainloop: 6 K-steps of 16, ldmatrix frag loads ----
        float c[2][4][4];
#pragma unroll
        for (int mf = 0; mf < 2; mf++)
#pragma unroll
            for (int nf = 0; nf < 4; nf++)
#pragma unroll
                for (int i = 0; i < 4; i++) c[mf][nf][i] = 0.f;

#pragma unroll
        for (int ks = 0; ks < 6; ks++) {
            uint32_t kofs = ks * 32;   // 8 words = 32 bytes per K-step
            uint32_t a[2][4];
            ldsm_x4(a[0][0], a[0][1], a[0][2], a[0][3], aAddr + kofs);
            ldsm_x4(a[1][0], a[1][1], a[1][2], a[1][3], aAddr + 16 * EA_W * 4 + kofs);
            uint32_t b[4][2];
            ldsm_x4(b[0][0], b[0][1], b[1][0], b[1][1], bAddr + kofs);
            ldsm_x4(b[2][0], b[2][1], b[3][0], b[3][1], bAddr + 16 * EB_W * 4 + kofs);
#pragma unroll
            for (int mf = 0; mf < 2; mf++)
#pragma unroll
                for (int nf = 0; nf < 4; nf++)
                    mma_f16(c[mf][nf], a[mf], b[nf]);
        }

        // ---- epilogue: +P[src] +Q[dst] +bias, ReLU, streaming store ----
#pragma unroll
        for (int mf = 0; mf < 2; mf++) {
#pragma unroll
            for (int half = 0; half < 2; half++) {
                int r = mw * 32 + mf * 16 + half * 8 + lq;
                int e = e0 + r;
                const float* P = g_PQ + (size_t)sv[mf][half] * 128;
                const float* Q = g_PQ + (size_t)dv[mf][half] * 128 + 64;
#pragma unroll
                for (int nf = 0; nf < 4; nf++) {
                    int col = nw * 32 + nf * 8 + 2 * lr;
                    float2 p = __ldg((const float2*)(P + col));
                    float2 q = __ldg((const float2*)(Q + col));
                    float2 bvv = *(const float2*)(bias + col);
                    float cx = c[mf][nf][half * 2 + 0];
                    float cy = c[mf][nf][half * 2 + 1];
                    float2 rv;
                    rv.x = fmaxf(cx + p.x + q.x + bvv.x, 0.f);
                    rv.y = fmaxf(cy + p.y + q.y + bvv.y, 0.f);
                    stg_cs(out + (size_t)e * 64 + col, rv);
                }
            }
        }
    }
}

// ---------------------------------------------------------------------------
extern "C" void kernel_launch(void* const* d_in, const int* in_sizes, int n_in,
                              void* d_out, int out_size) {
    const float* h   = (const float*)d_in[0];
    const float* e_h = (const float*)d_in[1];
    const float* ext = (const float*)d_in[2];
    const float* W1  = (const float*)d_in[3];
    const float* b1  = (const float*)d_in[4];
    const float* W2  = (const float*)d_in[5];
    const float* b2  = (const float*)d_in[6];
    const int*   src = (const int*)d_in[7];
    const int*   dst = (const int*)d_in[8];
    float* out = (float*)d_out;

    static bool attr_set = false;
    if (!attr_set) {
        cudaFuncSetAttribute(edge_kernel, cudaFuncAttributeMaxDynamicSharedMemorySize,
                             SMEM_WORDS * 4);
        cudaFuncSetAttribute(node_kernel, cudaFuncAttributeMaxDynamicSharedMemorySize,
                             NSM_WORDS * 4);
        attr_set = true;
    }

    prep_kernel<<<48, 256>>>(W1, b1, W2, b2);
    node_kernel<<<(N_NODES + 63) / 64, 256, NSM_WORDS * 4>>>(h);
    edge_kernel<<<EDGE_GRID, 256, SMEM_WORDS * 4>>>(e_h, ext, src, dst, out);
}